// round 16
// baseline (speedup 1.0000x reference)
#include <cuda_runtime.h>
#include <cuda_fp16.h>
#include <cstdint>

#define CIN 3
#define NY  31
#define POS 961
#define POq 48

// ---- smem layout (bytes) ----
#define SBIAS 0          // 48 floats
#define B0    1024       // B tile: 128 k-rows x 128B (48 halves used), swizzled, fp16
#define B1    17408
#define SMEM_BYTES 33792

__device__ __forceinline__ uint32_t smem_u32(const void* p) {
    uint32_t a;
    asm("{ .reg .u64 t; cvta.to.shared.u64 t, %1; cvt.u32.u64 %0, t; }" : "=r"(a) : "l"(p));
    return a;
}
__device__ __forceinline__ void ldsm_x4t(uint32_t& r0, uint32_t& r1, uint32_t& r2, uint32_t& r3,
                                         uint32_t a) {
    asm volatile("ldmatrix.sync.aligned.m8n8.x4.trans.shared.b16 {%0,%1,%2,%3}, [%4];"
                 : "=r"(r0), "=r"(r1), "=r"(r2), "=r"(r3) : "r"(a));
}
__device__ __forceinline__ void mma16816(float& d0, float& d1, float& d2, float& d3,
                                         uint32_t a0, uint32_t a1, uint32_t a2, uint32_t a3,
                                         uint32_t b0, uint32_t b1) {
    asm volatile("mma.sync.aligned.m16n8k16.row.col.f32.f16.f16.f32 "
                 "{%0,%1,%2,%3}, {%4,%5,%6,%7}, {%8,%9}, {%0,%1,%2,%3};"
                 : "+f"(d0), "+f"(d1), "+f"(d2), "+f"(d3)
                 : "r"(a0), "r"(a1), "r"(a2), "r"(a3), "r"(b0), "r"(b1));
}
__device__ __forceinline__ uint32_t pack_hi(float v0, float v1) {
    __half h0 = __float2half_rn(v0), h1 = __float2half_rn(v1);
    return (uint32_t)__half_as_ushort(h0) | ((uint32_t)__half_as_ushort(h1) << 16);
}
__device__ __forceinline__ void sts32(uint32_t a, uint32_t v) {
    asm volatile("st.shared.b32 [%0], %1;" :: "r"(a), "r"(v) : "memory");
}

extern __shared__ char smem[];

__global__ void __launch_bounds__(128, 5)
ttn_conv_hmma_kernel(const float* __restrict__ x,
                     const float* __restrict__ w,
                     const float* __restrict__ bias,
                     float* __restrict__ out)
{
    const int pos   = blockIdx.x >> 1;     // position; 2 CTAs per position
    const int mhalf = blockIdx.x & 1;      // which 64-row half of M=128
    const int xx    = pos / NY;
    const int yy    = pos - xx * NY;
    const int tid   = threadIdx.x;
    const int lane  = tid & 31;
    const int wid   = tid >> 5;
    const int base  = mhalf * 64;
    const uint32_t sb = smem_u32(smem);
    float* sbias = (float*)(smem + SBIAS);

    if (tid < POq) {
        int p = tid / 6, o = tid - p * 6;
        sbias[tid] = bias[((p * 31 + xx) * 31 + yy) * 6 + o];
    }

    const int bp  = tid >> 4;     // p block (0..7) for weight loads
    const int t16 = tid & 15;

    float D[24];
    #pragma unroll
    for (int i = 0; i < 24; i++) D[i] = 0.f;

    // ---- A register-resident: this thread's MMA-fragment rows (R14 mapping) ----
    const int row1 = base + wid * 16 + (lane >> 2);
    const int row2 = row1 + 8;
    const int cq = (lane & 3) >> 1;    // cv indices cq, cq+2
    const int dr = (lane & 1) * 2;     // dv indices dr, dr+1
    float av1[4], bv1[4], cd41[4];
    float av2[4], bv2[4], cd42[4];

    auto load_x = [&](int c) {
        const float* xp1 = x + ((size_t)row1 * CIN + c) * 4096 + xx * 32 + yy;
        const float* xp2 = x + ((size_t)row2 * CIN + c) * 4096 + xx * 32 + yy;
        #pragma unroll
        for (int i = 0; i < 4; i++) {
            av1[i] = xp1[i * 1024];          av2[i] = xp2[i * 1024];
            bv1[i] = xp1[i * 1024 + 32];     bv2[i] = xp2[i * 1024 + 32];
        }
        float c0a = xp1[cq * 1024 + 1],       c1a = xp1[(cq + 2) * 1024 + 1];
        float d0a = xp1[dr * 1024 + 33],      d1a = xp1[(dr + 1) * 1024 + 33];
        cd41[0] = c0a * d0a; cd41[1] = c0a * d1a; cd41[2] = c1a * d0a; cd41[3] = c1a * d1a;
        float c0b = xp2[cq * 1024 + 1],       c1b = xp2[(cq + 2) * 1024 + 1];
        float d0b = xp2[dr * 1024 + 33],      d1b = xp2[(dr + 1) * 1024 + 33];
        cd42[0] = c0b * d0b; cd42[1] = c0b * d1b; cd42[2] = c1b * d0b; cd42[3] = c1b * d1b;
    };

    float4 fb[3];   // quarter-stage weight batch (192 floats per p-block)
    // stage h (0..5) = half-c: weights floats [ (h&1)*768 + q*192 .. +192 ) of (c, bp)
    auto ldgB = [&](int h, int q) {
        int c = h >> 1;
        const float* gw = w + ((size_t)(c * 8 + bp) * POS + pos) * 1536 + (h & 1) * 768;
        #pragma unroll
        for (int r = 0; r < 3; r++) fb[r] = ((const float4*)gw)[t16 + 16 * (q * 3 + r)];
    };
    auto stsB = [&](int par, int q) {
        const uint32_t bh = sb + (par ? B1 : B0);
        #pragma unroll
        for (int r = 0; r < 3; r++) {
            const float* fp = &fb[r].x;
            const int rr = q * 3 + r;
            #pragma unroll
            for (int up = 0; up < 2; up++) {
                int e0 = t16 * 4 + up * 2 + rr * 64;  // even; e0%6 in {0,2,4} -> same-k pair
                int k  = e0 / 6, o = e0 - 6 * k;      // k 0..127
                uint32_t n   = (uint32_t)(bp * 6 + o);
                uint32_t off = (uint32_t)k * 128u + 16u * ((n >> 3) ^ ((uint32_t)k & 7u))
                             + (n & 7u) * 2u;
                sts32(bh + off, pack_hi(fp[up * 2], fp[up * 2 + 1]));
            }
        }
    };

    // ---- prologue: stage 0 into buffer 0 ----
    load_x(0);
    #pragma unroll
    for (int q = 0; q < 4; q++) { ldgB(0, q); stsB(0, q); }
    __syncthreads();

    // ---- pipeline: c (dynamic) x half (static) = 6 stages of K=128 ----
    #pragma unroll 1
    for (int c = 0; c < CIN; c++) {
        if (c) load_x(c);
        #pragma unroll
        for (int half = 0; half < 2; half++) {
            const int h   = c * 2 + half;
            const int buf = h & 1;
            const uint32_t bh = sb + (buf ? B1 : B0);

            // 4 sub-batches: ldg(next,q) -> compute 2 k16 steps -> sts(next,q)
            #pragma unroll
            for (int q = 0; q < 4; q++) {
                if (h < 5) ldgB(h + 1, q);
                #pragma unroll
                for (int sh = 0; sh < 2; sh++) {
                    const int s16 = q * 2 + sh;       // 0..7
                    uint32_t Bh[12];
                    uint32_t krow = (uint32_t)(s16 * 16 + ((lane >> 3) & 1) * 8 + (lane & 7));
                    #pragma unroll
                    for (int ntp = 0; ntp < 3; ntp++) {
                        uint32_t n    = (uint32_t)((ntp * 2 + (lane >> 4)) * 8);
                        uint32_t boff = krow * 128u + 16u * ((n >> 3) ^ (krow & 7u));
                        ldsm_x4t(Bh[ntp * 4], Bh[ntp * 4 + 1],
                                 Bh[ntp * 4 + 2], Bh[ntp * 4 + 3], bh + boff);
                    }
                    // A fragment from registers: ij = half*8 + s16
                    const float ab1 = av1[half * 2 + (s16 >> 2)] * bv1[s16 & 3];
                    const float ab2 = av2[half * 2 + (s16 >> 2)] * bv2[s16 & 3];
                    uint32_t Ah0 = pack_hi(ab1 * cd41[0], ab1 * cd41[1]);
                    uint32_t Ah1 = pack_hi(ab2 * cd42[0], ab2 * cd42[1]);
                    uint32_t Ah2 = pack_hi(ab1 * cd41[2], ab1 * cd41[3]);
                    uint32_t Ah3 = pack_hi(ab2 * cd42[2], ab2 * cd42[3]);
                    #pragma unroll
                    for (int nt = 0; nt < 6; nt++) {
                        float* d = D + nt * 4;
                        uint32_t b0 = (nt & 1) ? Bh[(nt >> 1) * 4 + 2] : Bh[(nt >> 1) * 4 + 0];
                        uint32_t b1 = (nt & 1) ? Bh[(nt >> 1) * 4 + 3] : Bh[(nt >> 1) * 4 + 1];
                        mma16816(d[0], d[1], d[2], d[3], Ah0, Ah1, Ah2, Ah3, b0, b1);
                    }
                }
                if (h < 5) stsB(buf ^ 1, q);
            }
            __syncthreads();
        }
    }

    // ---- epilogue ----
    #pragma unroll
    for (int nt = 0; nt < 6; nt++)
        #pragma unroll
        for (int r = 0; r < 4; r++) {
            int grow = base + wid * 16 + (lane >> 2) + ((r >= 2) ? 8 : 0);
            int q    = nt * 8 + (lane & 3) * 2 + (r & 1);
            out[((size_t)grow * POq + q) * POS + pos] = D[nt * 4 + r] + sbias[q];
        }
}

extern "C" void kernel_launch(void* const* d_in, const int* in_sizes, int n_in,
                              void* d_out, int out_size) {
    const float* x    = (const float*)d_in[0];
    const float* w    = (const float*)d_in[1];
    const float* bias = (const float*)d_in[2];
    float* out        = (float*)d_out;
    (void)in_sizes; (void)n_in; (void)out_size;

    cudaFuncSetAttribute(ttn_conv_hmma_kernel,
                         cudaFuncAttributeMaxDynamicSharedMemorySize, SMEM_BYTES);
    ttn_conv_hmma_kernel<<<POS * 2, 128, SMEM_BYTES>>>(x, w, bias, out);
}

// round 17
// speedup vs baseline: 1.0342x; 1.0342x over previous
#include <cuda_runtime.h>
#include <cuda_fp16.h>
#include <cstdint>

#define CIN 3
#define NY  31
#define POS 961
#define POq 48

// ---- smem layout (bytes) ----
#define SBIAS 0          // 48 floats
#define B0    1024       // B tile: 64 k-rows x 128B (48 halves used), swizzled, fp16
#define B1    9216
#define SMEM_BYTES 17408

__device__ __forceinline__ uint32_t smem_u32(const void* p) {
    uint32_t a;
    asm("{ .reg .u64 t; cvta.to.shared.u64 t, %1; cvt.u32.u64 %0, t; }" : "=r"(a) : "l"(p));
    return a;
}
__device__ __forceinline__ void ldsm_x4t(uint32_t& r0, uint32_t& r1, uint32_t& r2, uint32_t& r3,
                                         uint32_t a) {
    asm volatile("ldmatrix.sync.aligned.m8n8.x4.trans.shared.b16 {%0,%1,%2,%3}, [%4];"
                 : "=r"(r0), "=r"(r1), "=r"(r2), "=r"(r3) : "r"(a));
}
__device__ __forceinline__ void mma16816(float& d0, float& d1, float& d2, float& d3,
                                         uint32_t a0, uint32_t a1, uint32_t a2, uint32_t a3,
                                         uint32_t b0, uint32_t b1) {
    asm volatile("mma.sync.aligned.m16n8k16.row.col.f32.f16.f16.f32 "
                 "{%0,%1,%2,%3}, {%4,%5,%6,%7}, {%8,%9}, {%0,%1,%2,%3};"
                 : "+f"(d0), "+f"(d1), "+f"(d2), "+f"(d3)
                 : "r"(a0), "r"(a1), "r"(a2), "r"(a3), "r"(b0), "r"(b1));
}
__device__ __forceinline__ uint32_t pack_hi(float v0, float v1) {
    __half h0 = __float2half_rn(v0), h1 = __float2half_rn(v1);
    return (uint32_t)__half_as_ushort(h0) | ((uint32_t)__half_as_ushort(h1) << 16);
}
__device__ __forceinline__ void sts32(uint32_t a, uint32_t v) {
    asm volatile("st.shared.b32 [%0], %1;" :: "r"(a), "r"(v) : "memory");
}
__device__ __forceinline__ void pref_l2(const void* p) {
    asm volatile("prefetch.global.L2 [%0];" :: "l"(p));
}

extern __shared__ char smem[];

__global__ void __launch_bounds__(128, 5)
ttn_conv_hmma_kernel(const float* __restrict__ x,
                     const float* __restrict__ w,
                     const float* __restrict__ bias,
                     float* __restrict__ out)
{
    const int pos   = blockIdx.x >> 1;     // position; 2 CTAs per position
    const int mhalf = blockIdx.x & 1;      // which 64-row half of M=128
    const int xx    = pos / NY;
    const int yy    = pos - xx * NY;
    const int tid   = threadIdx.x;
    const int lane  = tid & 31;
    const int wid   = tid >> 5;
    const int base  = mhalf * 64;
    const uint32_t sb = smem_u32(smem);
    float* sbias = (float*)(smem + SBIAS);

    if (tid < POq) {
        int p = tid / 6, o = tid - p * 6;
        sbias[tid] = bias[((p * 31 + xx) * 31 + yy) * 6 + o];
    }

    const int bp  = tid >> 4;     // p block (0..7) for weight loads
    const int t16 = tid & 15;

    float D[24];
    #pragma unroll
    for (int i = 0; i < 24; i++) D[i] = 0.f;

    // ---- A is register-resident: this thread's MMA-fragment rows ----
    const int row1 = base + wid * 16 + (lane >> 2);   // global sample row
    const int row2 = row1 + 8;
    // lane's fixed kl set: {kl0, kl0+1, kl0+8, kl0+9}, kl0 = 2*(lane&3)
    const int cq = (lane & 3) >> 1;    // cv indices cq, cq+2
    const int dr = (lane & 1) * 2;     // dv indices dr, dr+1
    float av1[4], bv1[4], cd41[4];
    float av2[4], bv2[4], cd42[4];

    auto load_x = [&](int c) {
        const float* xp1 = x + ((size_t)row1 * CIN + c) * 4096 + xx * 32 + yy;
        const float* xp2 = x + ((size_t)row2 * CIN + c) * 4096 + xx * 32 + yy;
        #pragma unroll
        for (int i = 0; i < 4; i++) {
            av1[i] = xp1[i * 1024];          av2[i] = xp2[i * 1024];
            bv1[i] = xp1[i * 1024 + 32];     bv2[i] = xp2[i * 1024 + 32];
        }
        float c0a = xp1[cq * 1024 + 1],       c1a = xp1[(cq + 2) * 1024 + 1];
        float d0a = xp1[dr * 1024 + 33],      d1a = xp1[(dr + 1) * 1024 + 33];
        cd41[0] = c0a * d0a; cd41[1] = c0a * d1a; cd41[2] = c1a * d0a; cd41[3] = c1a * d1a;
        float c0b = xp2[cq * 1024 + 1],       c1b = xp2[(cq + 2) * 1024 + 1];
        float d0b = xp2[dr * 1024 + 33],      d1b = xp2[(dr + 1) * 1024 + 33];
        cd42[0] = c0b * d0b; cd42[1] = c0b * d1b; cd42[2] = c1b * d0b; cd42[3] = c1b * d1b;
    };

    float4 fb[6];                 // weight prefetch (384 floats / 16 thr / p-block)
    auto ldg_w = [&](int st) {    // stage st (0..11) covers 384 floats per p-block
        int c = st >> 2;
        const float* gw = w + ((size_t)(c * 8 + bp) * POS + pos) * 1536 + (st & 3) * 384;
        #pragma unroll
        for (int r = 0; r < 6; r++) fb[r] = ((const float4*)gw)[t16 + 16 * r];
    };
    // L2 prefetch of stage st's weight slab: 12 lines of 128B per p-block
    auto pref_w = [&](int st) {
        int c = st >> 2;
        const float* gw = w + ((size_t)(c * 8 + bp) * POS + pos) * 1536 + (st & 3) * 384;
        if (t16 < 12) pref_l2(gw + t16 * 32);
    };
    auto stageB = [&](int par) {  // write fp16 B tile to buffer `par` (R13 path)
        const uint32_t bh = sb + (par ? B1 : B0);
        #pragma unroll
        for (int r = 0; r < 6; r++) {
            const float* fp = &fb[r].x;
            #pragma unroll
            for (int up = 0; up < 2; up++) {
                int e0 = t16 * 4 + up * 2 + r * 64;   // even; e0%6 in {0,2,4} -> same-k pair
                int k  = e0 / 6, o = e0 - 6 * k;      // k 0..63
                uint32_t n   = (uint32_t)(bp * 6 + o);
                uint32_t off = (uint32_t)k * 128u + 16u * ((n >> 3) ^ ((uint32_t)k & 7u))
                             + (n & 7u) * 2u;
                sts32(bh + off, pack_hi(fp[up * 2], fp[up * 2 + 1]));
            }
        }
    };

    // ---- prologue ----
    pref_l2(&sbias[0]);           // no-op-ish warmup; keep order deterministic
    pref_w(1);
    load_x(0);
    ldg_w(0);
    stageB(0);
    __syncthreads();

    // ---- pipeline: c (dynamic) x sl (static) = 12 stages of K=64 ----
    #pragma unroll 1
    for (int c = 0; c < CIN; c++) {
        if (c) load_x(c);
        #pragma unroll
        for (int sl = 0; sl < 4; sl++) {
            const int st = c * 4 + sl;
            if (st + 2 < 12) pref_w(st + 2);       // pull st+2 into L2 (distance 2)
            if (st + 1 < 12) ldg_w(st + 1);        // distance 1; should now hit L2

            // ---- compute stage st from B[sl&1] + register A ----
            {
                const uint32_t bh = sb + ((sl & 1) ? B1 : B0);
                #pragma unroll
                for (int s16 = 0; s16 < 4; s16++) {
                    uint32_t Bh[12];
                    uint32_t krow = (uint32_t)(s16 * 16 + ((lane >> 3) & 1) * 8 + (lane & 7));
                    #pragma unroll
                    for (int ntp = 0; ntp < 3; ntp++) {
                        uint32_t n    = (uint32_t)((ntp * 2 + (lane >> 4)) * 8);
                        uint32_t boff = krow * 128u + 16u * ((n >> 3) ^ (krow & 7u));
                        ldsm_x4t(Bh[ntp * 4], Bh[ntp * 4 + 1],
                                 Bh[ntp * 4 + 2], Bh[ntp * 4 + 3], bh + boff);
                    }
                    // A fragment from registers: ij = sl*4 + s16 -> i = sl, j = s16
                    const float ab1 = av1[sl] * bv1[s16];
                    const float ab2 = av2[sl] * bv2[s16];
                    uint32_t Ah0 = pack_hi(ab1 * cd41[0], ab1 * cd41[1]);
                    uint32_t Ah1 = pack_hi(ab2 * cd42[0], ab2 * cd42[1]);
                    uint32_t Ah2 = pack_hi(ab1 * cd41[2], ab1 * cd41[3]);
                    uint32_t Ah3 = pack_hi(ab2 * cd42[2], ab2 * cd42[3]);
                    #pragma unroll
                    for (int nt = 0; nt < 6; nt++) {
                        float* d = D + nt * 4;
                        uint32_t b0 = (nt & 1) ? Bh[(nt >> 1) * 4 + 2] : Bh[(nt >> 1) * 4 + 0];
                        uint32_t b1 = (nt & 1) ? Bh[(nt >> 1) * 4 + 3] : Bh[(nt >> 1) * 4 + 1];
                        mma16816(d[0], d[1], d[2], d[3], Ah0, Ah1, Ah2, Ah3, b0, b1);
                    }
                }
            }

            if (st + 1 < 12) stageB((sl + 1) & 1);   // stage next B tile (other buffer)
            __syncthreads();
        }
    }

    // ---- epilogue ----
    #pragma unroll
    for (int nt = 0; nt < 6; nt++)
        #pragma unroll
        for (int r = 0; r < 4; r++) {
            int grow = base + wid * 16 + (lane >> 2) + ((r >= 2) ? 8 : 0);
            int q    = nt * 8 + (lane & 3) * 2 + (r & 1);
            out[((size_t)grow * POq + q) * POS + pos] = D[nt * 4 + r] + sbias[q];
        }
}

extern "C" void kernel_launch(void* const* d_in, const int* in_sizes, int n_in,
                              void* d_out, int out_size) {
    const float* x    = (const float*)d_in[0];
    const float* w    = (const float*)d_in[1];
    const float* bias = (const float*)d_in[2];
    float* out        = (float*)d_out;
    (void)in_sizes; (void)n_in; (void)out_size;

    cudaFuncSetAttribute(ttn_conv_hmma_kernel,
                         cudaFuncAttributeMaxDynamicSharedMemorySize, SMEM_BYTES);
    ttn_conv_hmma_kernel<<<POS * 2, 128, SMEM_BYTES>>>(x, w, bias, out);
}